// round 5
// baseline (speedup 1.0000x reference)
#include <cuda_runtime.h>
#include <cstdint>

#define BB 8
#define FF 2048
#define LL 1024
#define THRESH 0.81f
#define BN_EPS 1e-5f

// scratch (device globals per allocation rules)
__device__ float g_h[BB * FF];     // raw pooled prelu means (k1 output)
__device__ float g_hbn[BB * FF];   // BN'd h (k23 output)
__device__ float g_dinv[BB * FF];  // rsqrt(degree)

// ---------------- k1: prelu + mean over L (warp-per-row) ----------------
// grid = BB*FF/16 = 1024 blocks, 512 threads = 16 warps. MLP=8 per lane.
// __ldcs: x is read-once streaming data -> evict-first, keep L2 clean.
__global__ void k1_rowmean(const float* __restrict__ x,
                           const float* __restrict__ w1p) {
    const float w1 = w1p[0];
    const int warp = threadIdx.x >> 5, lane = threadIdx.x & 31;
    const int row = blockIdx.x * 16 + warp;
    const float4* xr = (const float4*)(x + (size_t)row * LL);

    float4 v[8];
    #pragma unroll
    for (int j = 0; j < 8; j++) v[j] = __ldcs(&xr[lane + 32 * j]);

    float s = 0.f;
    #pragma unroll
    for (int j = 0; j < 8; j++) {
        s += (v[j].x >= 0.f) ? v[j].x : w1 * v[j].x;
        s += (v[j].y >= 0.f) ? v[j].y : w1 * v[j].y;
        s += (v[j].z >= 0.f) ? v[j].z : w1 * v[j].z;
        s += (v[j].w >= 0.f) ? v[j].w : w1 * v[j].w;
    }
    #pragma unroll
    for (int o = 16; o; o >>= 1) s += __shfl_down_sync(0xffffffffu, s, o);
    if (lane == 0) g_h[row] = s * (1.0f / LL);
}

// ---------------- k23: fused BatchNorm + degree ----------------
// grid (FF/64, BB) = (32, 8) = 256 blocks, 512 threads = 16 warps.
// Each block redundantly computes BN for ALL channels of batch b into smem
// (L2-hit loads), writes its own 64-column slice of g_hbn, then warp w
// counts degree for rows bx*64 + w*4 .. +3 against smem.
#define SLICE 64
__global__ void k23_bn_deg(const float* __restrict__ bw,
                           const float* __restrict__ bb) {
    const int b = blockIdx.y;
    __shared__ float sh[FF];
    const int tid = threadIdx.x;

    // BN: 4 channels per thread (coalesced, f = tid + c*512)
    #pragma unroll
    for (int c = 0; c < 4; c++) {
        const int f = tid + c * 512;
        float v[BB];
        float mu = 0.f;
        #pragma unroll
        for (int q = 0; q < BB; q++) { v[q] = g_h[q * FF + f]; mu += v[q]; }
        mu *= (1.0f / BB);
        float var = 0.f;
        #pragma unroll
        for (int q = 0; q < BB; q++) { float d = v[q] - mu; var += d * d; }
        var *= (1.0f / BB);
        const float hv = (v[b] - mu) * rsqrtf(var + BN_EPS) * bw[f] + bb[f];
        sh[f] = hv;
        if ((f >> 6) == (int)blockIdx.x) g_hbn[b * FF + f] = hv;
    }
    __syncthreads();

    // degree count: warp w -> 4 rows
    const int warp = tid >> 5, lane = tid & 31;
    const int nbase = blockIdx.x * SLICE + warp * 4;
    float hn[4], cnt[4] = {0.f, 0.f, 0.f, 0.f};
    #pragma unroll
    for (int r = 0; r < 4; r++) hn[r] = sh[nbase + r];

    const float4* s4 = (const float4*)sh;
    #pragma unroll 4
    for (int i = lane; i < FF / 4; i += 32) {
        float4 v = s4[i];
        #pragma unroll
        for (int r = 0; r < 4; r++) {
            cnt[r] += (hn[r] * v.x > THRESH) ? 1.f : 0.f;
            cnt[r] += (hn[r] * v.y > THRESH) ? 1.f : 0.f;
            cnt[r] += (hn[r] * v.z > THRESH) ? 1.f : 0.f;
            cnt[r] += (hn[r] * v.w > THRESH) ? 1.f : 0.f;
        }
    }
    #pragma unroll
    for (int r = 0; r < 4; r++) {
        #pragma unroll
        for (int o = 16; o; o >>= 1)
            cnt[r] += __shfl_down_sync(0xffffffffu, cnt[r], o);
    }
    if (lane == 0) {
        #pragma unroll
        for (int r = 0; r < 4; r++)
            g_dinv[b * FF + nbase + r] = rsqrtf(cnt[r] + 1.0f);  // +1 identity
    }
}

// ---------------- k4: expand output (direct STG, measured-best) ----------------
// out[b,n,m] = dinv_n*dinv_m*[h_n*h_m > T] + (n==m)*dinv_n^2
// grid (FF/TILE_N, BB) = (128, 8), block 256; each thread owns 8 m-columns.
#define TILE_N 16
__global__ void k4_out(float* __restrict__ out) {
    const int b = blockIdx.y;
    const int n0 = blockIdx.x * TILE_N;
    const float* __restrict__ hb = g_hbn + b * FF;
    const float* __restrict__ db = g_dinv + b * FF;

    // per-thread m columns: float4 indices q0 = tid, q1 = tid+256
    float hm[8], dm[8];
    #pragma unroll
    for (int j = 0; j < 2; j++) {
        const int q = threadIdx.x + j * 256;
        float4 h4 = ((const float4*)hb)[q];
        float4 d4 = ((const float4*)db)[q];
        hm[j * 4 + 0] = h4.x; hm[j * 4 + 1] = h4.y;
        hm[j * 4 + 2] = h4.z; hm[j * 4 + 3] = h4.w;
        dm[j * 4 + 0] = d4.x; dm[j * 4 + 1] = d4.y;
        dm[j * 4 + 2] = d4.z; dm[j * 4 + 3] = d4.w;
    }

    float* outb = out + (size_t)b * FF * FF;
    #pragma unroll 4
    for (int nn = 0; nn < TILE_N; nn++) {
        const int n = n0 + nn;
        const float hn = hb[n];        // uniform -> broadcast, L1 hit
        const float dn = db[n];
        const float diag = dn * dn;
        float4* orow = (float4*)(outb + (size_t)n * FF);
        #pragma unroll
        for (int j = 0; j < 2; j++) {
            const int q = threadIdx.x + j * 256;
            const int mg = q * 4;
            float4 r;
            float* rp = &r.x;
            #pragma unroll
            for (int k = 0; k < 4; k++) {
                float v = (hn * hm[j * 4 + k] > THRESH) ? dn * dm[j * 4 + k] : 0.f;
                if (mg + k == n) v += diag;
                rp[k] = v;
            }
            orow[q] = r;
        }
    }
}

extern "C" void kernel_launch(void* const* d_in, const int* in_sizes, int n_in,
                              void* d_out, int out_size) {
    const float* x   = (const float*)d_in[0];
    const float* w1  = (const float*)d_in[1];
    // d_in[2] = prelu2_w: unused — A_hat is provably nonnegative, PReLU is identity
    const float* bnw = (const float*)d_in[3];
    const float* bnb = (const float*)d_in[4];
    float* out = (float*)d_out;

    k1_rowmean<<<BB * FF / 16, 512>>>(x, w1);
    k23_bn_deg<<<dim3(FF / SLICE, BB), 512>>>(bnw, bnb);
    k4_out<<<dim3(FF / TILE_N, BB), 256>>>(out);
}